// round 8
// baseline (speedup 1.0000x reference)
#include <cuda_runtime.h>
#include <cuda_bf16.h>
#include <cstdint>

#define BATCH 4
#define SEQ 2048
#define DIM 1024
#define HEADS 16
#define DHEAD 64
#define INNER 1024
#define TOKENS (BATCH * SEQ)
#define ATT_SCALE 0.125f

// ---------------------------------------------------------------------------
// Scratch (allocation-free device globals)
// ---------------------------------------------------------------------------
__device__ __nv_bfloat16 g_xh[TOKENS * DIM];
__device__ __nv_bfloat16 g_xl[TOKENS * DIM];
__device__ __nv_bfloat16 g_qh[TOKENS * INNER];
__device__ __nv_bfloat16 g_ql[TOKENS * INNER];
__device__ __nv_bfloat16 g_kh[TOKENS * INNER];
__device__ __nv_bfloat16 g_kl[TOKENS * INNER];
__device__ __nv_bfloat16 g_vh[TOKENS * INNER];
__device__ __nv_bfloat16 g_vl[TOKENS * INNER];
__device__ __nv_bfloat16 g_oh[TOKENS * INNER];
__device__ __nv_bfloat16 g_ol[TOKENS * INNER];
// fused QKV weight, transposed+split: rows 0-1023 = Wq^T, 1024-3071 = Wkv^T
__device__ __nv_bfloat16 g_wth[3 * INNER * DIM];
__device__ __nv_bfloat16 g_wtl[3 * INNER * DIM];
__device__ __nv_bfloat16 g_woth[DIM * INNER];
__device__ __nv_bfloat16 g_wotl[DIM * INNER];

// ---------------------------------------------------------------------------
// Helpers (base-target PTX only: ldmatrix / mma.sync / cp.async)
// ---------------------------------------------------------------------------
__device__ __forceinline__ uint32_t smem_u32(const void* p) {
    uint32_t a;
    asm("{ .reg .u64 t; cvta.to.shared.u64 t, %1; cvt.u32.u64 %0, t; }"
        : "=r"(a) : "l"(p));
    return a;
}

__device__ __forceinline__ void ldm_x4(uint32_t* r, uint32_t addr) {
    asm volatile("ldmatrix.sync.aligned.m8n8.x4.shared.b16 {%0,%1,%2,%3}, [%4];"
                 : "=r"(r[0]), "=r"(r[1]), "=r"(r[2]), "=r"(r[3]) : "r"(addr));
}

__device__ __forceinline__ void ldm_x4_t(uint32_t* r, uint32_t addr) {
    asm volatile("ldmatrix.sync.aligned.m8n8.x4.trans.shared.b16 {%0,%1,%2,%3}, [%4];"
                 : "=r"(r[0]), "=r"(r[1]), "=r"(r[2]), "=r"(r[3]) : "r"(addr));
}

__device__ __forceinline__ void mma16816(float* c, const uint32_t* a, const uint32_t* b) {
    asm volatile(
        "mma.sync.aligned.m16n8k16.row.col.f32.bf16.bf16.f32 "
        "{%0,%1,%2,%3}, {%4,%5,%6,%7}, {%8,%9}, {%0,%1,%2,%3};"
        : "+f"(c[0]), "+f"(c[1]), "+f"(c[2]), "+f"(c[3])
        : "r"(a[0]), "r"(a[1]), "r"(a[2]), "r"(a[3]), "r"(b[0]), "r"(b[1]));
}

__device__ __forceinline__ void cp_async16(uint32_t saddr, const void* gaddr) {
    asm volatile("cp.async.cg.shared.global [%0], [%1], 16;"
                 :: "r"(saddr), "l"(gaddr) : "memory");
}
__device__ __forceinline__ void cp_commit() {
    asm volatile("cp.async.commit_group;" ::: "memory");
}
template <int N>
__device__ __forceinline__ void cp_wait() {
    asm volatile("cp.async.wait_group %0;" :: "n"(N) : "memory");
}

__device__ __forceinline__ void bf16_split(float a, __nv_bfloat16& h, __nv_bfloat16& l) {
    h = __float2bfloat16_rn(a);
    l = __float2bfloat16_rn(a - __bfloat162float(h));
}

__device__ __forceinline__ void pack_split(float x, float y, uint32_t& hi, uint32_t& lo) {
    __nv_bfloat16 hx = __float2bfloat16_rn(x);
    __nv_bfloat16 hy = __float2bfloat16_rn(y);
    __nv_bfloat162 H(hx, hy);
    __nv_bfloat162 L(__float2bfloat16_rn(x - __bfloat162float(hx)),
                     __float2bfloat16_rn(y - __bfloat162float(hy)));
    hi = *(uint32_t*)&H;
    lo = *(uint32_t*)&L;
}

// 128B-row swizzle (flash tiles): 8 x 16B chunks per row, chunk ^= row (mod 8)
#define FSWZ(row, chunk) (((row) << 7) + ((((chunk) ^ (row)) & 7) << 4))
// 64B-row swizzle (gemm tiles): 4 x 16B chunks per row, chunk ^= (row>>1)&3
#define HSWZ(row, chunk) (((row) << 6) + (((chunk) ^ (((row) >> 1) & 3)) << 4))

// ---------------------------------------------------------------------------
// Prep: split x into bf16 hi/lo
// ---------------------------------------------------------------------------
__global__ void split_x_kernel(const float* __restrict__ in,
                               __nv_bfloat16* __restrict__ oh,
                               __nv_bfloat16* __restrict__ ol) {
    int i = (blockIdx.x * blockDim.x + threadIdx.x) * 4;
    float4 v = *(const float4*)(in + i);
    __nv_bfloat16 h0, h1, h2, h3, l0, l1, l2, l3;
    bf16_split(v.x, h0, l0); bf16_split(v.y, h1, l1);
    bf16_split(v.z, h2, l2); bf16_split(v.w, h3, l3);
    *(__nv_bfloat162*)(oh + i)     = __nv_bfloat162(h0, h1);
    *(__nv_bfloat162*)(oh + i + 2) = __nv_bfloat162(h2, h3);
    *(__nv_bfloat162*)(ol + i)     = __nv_bfloat162(l0, l1);
    *(__nv_bfloat162*)(ol + i + 2) = __nv_bfloat162(l2, l3);
}

// ---------------------------------------------------------------------------
// Prep: transpose W[K,N] -> WT[N,K] split into bf16 hi/lo
// ---------------------------------------------------------------------------
__global__ void transpose_split_kernel(const float* __restrict__ W,
                                       __nv_bfloat16* __restrict__ WTh,
                                       __nv_bfloat16* __restrict__ WTl,
                                       int K, int N) {
    __shared__ float t[32][33];
    int k0 = blockIdx.x * 32, n0 = blockIdx.y * 32;
    int x = threadIdx.x, y = threadIdx.y;
#pragma unroll
    for (int j = 0; j < 32; j += 8)
        t[y + j][x] = W[(size_t)(k0 + y + j) * N + n0 + x];
    __syncthreads();
#pragma unroll
    for (int j = 0; j < 32; j += 8) {
        float a = t[x][y + j];
        __nv_bfloat16 h, l;
        bf16_split(a, h, l);
        size_t o = (size_t)(n0 + y + j) * K + k0 + x;
        WTh[o] = h; WTl[o] = l;
    }
}

// ---------------------------------------------------------------------------
// HMMA bf16x3 GEMM:  C[M,N] = A[M,K] @ BT[N,K]^T  (fp32 accumulate)
// CTA tile 128x256, 256 threads, 8 warps = 2(M) x 4(N), warp tile 64x64.
// Per k16 step: 16 LDSM.x4 feed 96 MMAs (ratio 6:1, 2x the old 3:1).
// MMAs ordered term-outer (hh then hl then lh) to break accumulator chains.
// k-block 32, 3-stage cp.async ring (144 KB smem), one sync per k-block.
// Output: fp32 Cf (+bias) if non-null; else 3-way bf16 hi/lo split routed by
// 1024-wide column segment (seg0 scaled by ATT_SCALE -> q, seg1 -> k, seg2 -> v).
// ---------------------------------------------------------------------------
#define HT_TK 32
#define HT_TILE_A 8192                   // [128 rows][32 bf16]
#define HT_TILE_B 16384                  // [256 rows][32 bf16]
#define HT_STAGE (2 * HT_TILE_A + 2 * HT_TILE_B)   // 48 KB
#define HT_SMEM (3 * HT_STAGE)                     // 144 KB

__global__ __launch_bounds__(256)
void gemm_tc(const __nv_bfloat16* __restrict__ Ah,
             const __nv_bfloat16* __restrict__ Al,
             const __nv_bfloat16* __restrict__ Bh,
             const __nv_bfloat16* __restrict__ Bl,
             float* __restrict__ Cf, const float* __restrict__ bias,
             __nv_bfloat16* __restrict__ S0h, __nv_bfloat16* __restrict__ S0l,
             __nv_bfloat16* __restrict__ S1h, __nv_bfloat16* __restrict__ S1l,
             __nv_bfloat16* __restrict__ S2h, __nv_bfloat16* __restrict__ S2l,
             int N, int K)
{
    extern __shared__ char smem[];
    const uint32_t sb = smem_u32(smem);
    const int tid = threadIdx.x;
    const int wid = tid >> 5;
    const int lane = tid & 31;
    const int m0 = blockIdx.y * 128;
    const int n0 = blockIdx.x * 256;
    const int nkb = K / HT_TK;

    const int wm = (wid & 1) * 64;    // warp M offset (2 groups)
    const int wn = (wid >> 1) * 64;   // warp N offset (4 groups)

    // loader mappings
    const int larow = tid >> 1;              // A: row, 2 chunks/thread/tile
    const int lach  = (tid & 1) * 2;
    const int lbrow = tid;                   // B: row, 4 chunks/thread/tile

    auto load_stage = [&](int st, int kb) {
        const uint32_t stg = sb + st * HT_STAGE;
        const size_t kc = (size_t)kb * HT_TK;
        const __nv_bfloat16* pa_h = Ah + (size_t)(m0 + larow) * K + kc;
        const __nv_bfloat16* pa_l = Al + (size_t)(m0 + larow) * K + kc;
#pragma unroll
        for (int c = 0; c < 2; c++) {
            cp_async16(stg + HSWZ(larow, lach + c), pa_h + (lach + c) * 8);
            cp_async16(stg + HT_TILE_A + HSWZ(larow, lach + c), pa_l + (lach + c) * 8);
        }
        const uint32_t bstg = stg + 2 * HT_TILE_A;
        const __nv_bfloat16* pb_h = Bh + (size_t)(n0 + lbrow) * K + kc;
        const __nv_bfloat16* pb_l = Bl + (size_t)(n0 + lbrow) * K + kc;
#pragma unroll
        for (int c = 0; c < 4; c++) {
            cp_async16(bstg + HSWZ(lbrow, c), pb_h + c * 8);
            cp_async16(bstg + HT_TILE_B + HSWZ(lbrow, c), pb_l + c * 8);
        }
    };

    float acc[4][8][4];
#pragma unroll
    for (int i = 0; i < 4; i++)
#pragma unroll
        for (int j = 0; j < 8; j++)
#pragma unroll
            for (int e = 0; e < 4; e++) acc[i][j][e] = 0.f;

    const int a_row = lane & 15;
    const int a_chk = lane >> 4;
    const int b_row = (lane & 7) + ((lane >> 4) << 3);
    const int b_chk = (lane >> 3) & 1;

    load_stage(0, 0); cp_commit();
    load_stage(1, 1); cp_commit();

    for (int kb = 0; kb < nkb; kb++) {
        if (kb + 1 < nkb) cp_wait<1>(); else cp_wait<0>();
        __syncthreads();

        // prefetch kb+2 into the stage freed at the end of iter kb-1
        if (kb + 2 < nkb) {
            load_stage((kb + 2) % 3, kb + 2);
            cp_commit();
        }

        const uint32_t stg = sb + (kb % 3) * HT_STAGE;
        const uint32_t sAh = stg;
        const uint32_t sAl = stg + HT_TILE_A;
        const uint32_t sBh = stg + 2 * HT_TILE_A;
        const uint32_t sBl = stg + 2 * HT_TILE_A + HT_TILE_B;

#pragma unroll
        for (int kk = 0; kk < 2; kk++) {
            uint32_t ah[4][4], al[4][4], bh[4][4], bl[4][4];
#pragma unroll
            for (int mt = 0; mt < 4; mt++) {
                int r = wm + mt * 16 + a_row;
                int c = kk * 2 + a_chk;
                ldm_x4(ah[mt], sAh + HSWZ(r, c));
                ldm_x4(al[mt], sAl + HSWZ(r, c));
            }
#pragma unroll
            for (int ng = 0; ng < 4; ng++) {
                int r = wn + ng * 16 + b_row;
                int c = kk * 2 + b_chk;
                ldm_x4(bh[ng], sBh + HSWZ(r, c));
                ldm_x4(bl[ng], sBl + HSWZ(r, c));
            }
            // term-outer: hh, hl, lh — 32 independent MMAs between acc reuse
#pragma unroll
            for (int mt = 0; mt < 4; mt++)
#pragma unroll
                for (int nt = 0; nt < 8; nt++)
                    mma16816(acc[mt][nt], ah[mt], &bh[nt >> 1][(nt & 1) * 2]);
#pragma unroll
            for (int mt = 0; mt < 4; mt++)
#pragma unroll
                for (int nt = 0; nt < 8; nt++)
                    mma16816(acc[mt][nt], ah[mt], &bl[nt >> 1][(nt & 1) * 2]);
#pragma unroll
            for (int mt = 0; mt < 4; mt++)
#pragma unroll
                for (int nt = 0; nt < 8; nt++)
                    mma16816(acc[mt][nt], al[mt], &bh[nt >> 1][(nt & 1) * 2]);
        }
        __syncthreads();
    }

    const int erow = lane >> 2;
    const int ecol = (lane & 3) * 2;

    if (Cf) {
        // fp32 output with bias
#pragma unroll
        for (int mt = 0; mt < 4; mt++) {
#pragma unroll
            for (int nt = 0; nt < 8; nt++) {
                int gcol = n0 + wn + nt * 8 + ecol;
                float b0 = 0.f, b1 = 0.f;
                if (bias) { b0 = bias[gcol]; b1 = bias[gcol + 1]; }
                int r0 = m0 + wm + mt * 16 + erow;
                float2 v0 = make_float2(acc[mt][nt][0] + b0, acc[mt][nt][1] + b1);
                float2 v1 = make_float2(acc[mt][nt][2] + b0, acc[mt][nt][3] + b1);
                *(float2*)(Cf + (size_t)r0 * N + gcol)       = v0;
                *(float2*)(Cf + (size_t)(r0 + 8) * N + gcol) = v1;
            }
        }
    } else {
        // 3-way split bf16 output, 1024-wide segments (q scaled, k, v).
        // n0 is a multiple of 256 so the whole CTA stays in one segment.
        const int seg = n0 >> 10;
        const int c0 = n0 & 1023;
        const float oscale = (seg == 0) ? ATT_SCALE : 1.0f;
        __nv_bfloat16* Oh = (seg == 0) ? S0h : (seg == 1) ? S1h : S2h;
        __nv_bfloat16* Ol = (seg == 0) ? S0l : (seg == 1) ? S1l : S2l;
#pragma unroll
        for (int mt = 0; mt < 4; mt++) {
#pragma unroll
            for (int nt = 0; nt < 8; nt++) {
                int r0 = m0 + wm + mt * 16 + erow;
                int lcol = c0 + wn + nt * 8 + ecol;
                uint32_t h0, l0h, h1, l1h;
                pack_split(acc[mt][nt][0] * oscale, acc[mt][nt][1] * oscale, h0, l0h);
                pack_split(acc[mt][nt][2] * oscale, acc[mt][nt][3] * oscale, h1, l1h);
                *(uint32_t*)(Oh + (size_t)r0 * 1024 + lcol)       = h0;
                *(uint32_t*)(Ol + (size_t)r0 * 1024 + lcol)       = l0h;
                *(uint32_t*)(Oh + (size_t)(r0 + 8) * 1024 + lcol) = h1;
                *(uint32_t*)(Ol + (size_t)(r0 + 8) * 1024 + lcol) = l1h;
            }
        }
    }
}

// ---------------------------------------------------------------------------
// Flash attention on mma.sync, bf16x3 split for S and P·V (unchanged).
// ---------------------------------------------------------------------------
#define FA_BQ 128
#define FA_BK 64
#define FA_NC (SEQ / FA_BK)
#define FA_SMEM (32768 + 3 * 32768)

__global__ __launch_bounds__(256, 1)
void flash_tc(const __nv_bfloat16* __restrict__ Qh, const __nv_bfloat16* __restrict__ Ql,
              const __nv_bfloat16* __restrict__ Kh, const __nv_bfloat16* __restrict__ Kl,
              const __nv_bfloat16* __restrict__ Vh, const __nv_bfloat16* __restrict__ Vl,
              __nv_bfloat16* __restrict__ Oh, __nv_bfloat16* __restrict__ Ol)
{
    extern __shared__ char smem[];
    const uint32_t sb = smem_u32(smem);
    const int tid = threadIdx.x;
    const int wid = tid >> 5;
    const int lane = tid & 31;
    const int qt = blockIdx.x;
    const int b  = blockIdx.y >> 4;
    const int h  = blockIdx.y & 15;

    const size_t base_q  = (size_t)(b * SEQ + qt * FA_BQ) * INNER + h * DHEAD;
    const size_t base_kv = (size_t)b * SEQ * INNER + h * DHEAD;

    {
        int row = tid >> 3, chunk = tid & 7;
#pragma unroll
        for (int p = 0; p < 4; p++) {
            int r = row + p * 32;
            size_t go = base_q + (size_t)r * INNER + chunk * 8;
            cp_async16(sb +         FSWZ(r, chunk), Qh + go);
            cp_async16(sb + 16384 + FSWZ(r, chunk), Ql + go);
        }
    }
    auto load_kv = [&](int st, int kc) {
        const uint32_t stg = sb + 32768 + st * 32768;
        int row = tid >> 3, chunk = tid & 7;
        size_t gk = base_kv + (size_t)(kc * FA_BK) * INNER + chunk * 8;
#pragma unroll
        for (int p = 0; p < 2; p++) {
            int r = row + p * 32;
            size_t go = gk + (size_t)r * INNER;
            cp_async16(stg +         FSWZ(r, chunk), Kh + go);
            cp_async16(stg +  8192 + FSWZ(r, chunk), Kl + go);
            cp_async16(stg + 16384 + FSWZ(r, chunk), Vh + go);
            cp_async16(stg + 24576 + FSWZ(r, chunk), Vl + go);
        }
    };
    load_kv(0, 0); cp_commit();
    load_kv(1, 1); cp_commit();

    uint32_t qfh[4][4], qfl[4][4];
    float oacc[8][4];
#pragma unroll
    for (int j = 0; j < 8; j++)
#pragma unroll
        for (int e = 0; e < 4; e++) oacc[j][e] = 0.f;
    float m0 = -1e30f, m1 = -1e30f, l0 = 0.f, l1 = 0.f;

    for (int kc = 0; kc < FA_NC; kc++) {
        if (kc + 1 < FA_NC) cp_wait<1>(); else cp_wait<0>();
        __syncthreads();

        if (kc == 0) {
#pragma unroll
            for (int kk = 0; kk < 4; kk++) {
                int r = wid * 16 + (lane & 15);
                int c = 2 * kk + (lane >> 4);
                ldm_x4(qfh[kk], sb +         FSWZ(r, c));
                ldm_x4(qfl[kk], sb + 16384 + FSWZ(r, c));
            }
        }
        const uint32_t stg = sb + 32768 + (kc % 3) * 32768;

        float sacc[8][4];
#pragma unroll
        for (int t = 0; t < 8; t++)
#pragma unroll
            for (int e = 0; e < 4; e++) sacc[t][e] = 0.f;
#pragma unroll
        for (int kk = 0; kk < 4; kk++) {
            uint32_t kbh[4][4], kbl[4][4];
#pragma unroll
            for (int G = 0; G < 4; G++) {
                int r = 16 * G + ((lane >> 4) << 3) + (lane & 7);
                int c = 2 * kk + ((lane >> 3) & 1);
                ldm_x4(kbh[G], stg +        FSWZ(r, c));
                ldm_x4(kbl[G], stg + 8192 + FSWZ(r, c));
            }
#pragma unroll
            for (int t = 0; t < 8; t++) {
                const int G = t >> 1, hf = (t & 1) * 2;
                mma16816(sacc[t], qfh[kk], &kbh[G][hf]);
                mma16816(sacc[t], qfh[kk], &kbl[G][hf]);
                mma16816(sacc[t], qfl[kk], &kbh[G][hf]);
            }
        }

        float mx0 = -1e30f, mx1 = -1e30f;
#pragma unroll
        for (int t = 0; t < 8; t++) {
            mx0 = fmaxf(mx0, fmaxf(sacc[t][0], sacc[t][1]));
            mx1 = fmaxf(mx1, fmaxf(sacc[t][2], sacc[t][3]));
        }
        mx0 = fmaxf(mx0, __shfl_xor_sync(0xffffffffu, mx0, 1));
        mx0 = fmaxf(mx0, __shfl_xor_sync(0xffffffffu, mx0, 2));
        mx1 = fmaxf(mx1, __shfl_xor_sync(0xffffffffu, mx1, 1));
        mx1 = fmaxf(mx1, __shfl_xor_sync(0xffffffffu, mx1, 2));
        float mn0 = fmaxf(m0, mx0), mn1 = fmaxf(m1, mx1);
        float a0 = __expf(m0 - mn0), a1 = __expf(m1 - mn1);
        m0 = mn0; m1 = mn1;
        float s0 = 0.f, s1 = 0.f;
#pragma unroll
        for (int t = 0; t < 8; t++) {
            sacc[t][0] = __expf(sacc[t][0] - mn0); s0 += sacc[t][0];
            sacc[t][1] = __expf(sacc[t][1] - mn0); s0 += sacc[t][1];
            sacc[t][2] = __expf(sacc[t][2] - mn1); s1 += sacc[t][2];
            sacc[t][3] = __expf(sacc[t][3] - mn1); s1 += sacc[t][3];
        }
        s0 += __shfl_xor_sync(0xffffffffu, s0, 1);
        s0 += __shfl_xor_sync(0xffffffffu, s0, 2);
        s1 += __shfl_xor_sync(0xffffffffu, s1, 1);
        s1 += __shfl_xor_sync(0xffffffffu, s1, 2);
        l0 = l0 * a0 + s0;
        l1 = l1 * a1 + s1;
#pragma unroll
        for (int j = 0; j < 8; j++) {
            oacc[j][0] *= a0; oacc[j][1] *= a0;
            oacc[j][2] *= a1; oacc[j][3] *= a1;
        }

#pragma unroll
        for (int s = 0; s < 4; s++) {
            uint32_t ah[4], al[4];
            pack_split(sacc[2 * s][0],     sacc[2 * s][1],     ah[0], al[0]);
            pack_split(sacc[2 * s][2],     sacc[2 * s][3],     ah[1], al[1]);
            pack_split(sacc[2 * s + 1][0], sacc[2 * s + 1][1], ah[2], al[2]);
            pack_split(sacc[2 * s + 1][2], sacc[2 * s + 1][3], ah[3], al[3]);
            uint32_t vbh[4][4], vbl[4][4];
#pragma unroll
            for (int J = 0; J < 4; J++) {
                int r = 16 * s + (lane & 7) + ((lane >> 3) & 1) * 8;
                int c = 2 * J + (lane >> 4);
                ldm_x4_t(vbh[J], stg + 16384 + FSWZ(r, c));
                ldm_x4_t(vbl[J], stg + 24576 + FSWZ(r, c));
            }
#pragma unroll
            for (int j = 0; j < 8; j++) {
                const int J = j >> 1, hf = (j & 1) * 2;
                mma16816(oacc[j], ah, &vbh[J][hf]);
                mma16816(oacc[j], ah, &vbl[J][hf]);
                mma16816(oacc[j], al, &vbh[J][hf]);
            }
        }

        if (kc + 2 < FA_NC) {
            load_kv((kc + 2) % 3, kc + 2);
            cp_commit();
        }
    }

    float inv0 = 1.f / l0, inv1 = 1.f / l1;
    int r = lane >> 2;
    size_t row0 = (size_t)(b * SEQ + qt * FA_BQ + wid * 16 + r);
    size_t row1 = row0 + 8;
    int colb = h * DHEAD + (lane & 3) * 2;
#pragma unroll
    for (int j = 0; j < 8; j++) {
        size_t o0 = row0 * INNER + colb + j * 8;
        size_t o1 = row1 * INNER + colb + j * 8;
        uint32_t h0, lo0, h1, lo1;
        pack_split(oacc[j][0] * inv0, oacc[j][1] * inv0, h0, lo0);
        pack_split(oacc[j][2] * inv1, oacc[j][3] * inv1, h1, lo1);
        *(uint32_t*)(Oh + o0) = h0;
        *(uint32_t*)(Ol + o0) = lo0;
        *(uint32_t*)(Oh + o1) = h1;
        *(uint32_t*)(Ol + o1) = lo1;
    }
}

// ---------------------------------------------------------------------------
extern "C" void kernel_launch(void* const* d_in, const int* in_sizes, int n_in,
                              void* d_out, int out_size)
{
    const float* x   = (const float*)d_in[0];
    const float* Wq  = (const float*)d_in[1];
    const float* Wkv = (const float*)d_in[2];
    const float* Wo  = (const float*)d_in[3];
    const float* bo  = (const float*)d_in[4];
    float* out = (float*)d_out;

    __nv_bfloat16 *xh, *xl, *qh, *ql, *kh, *kl, *vh, *vl, *oh, *ol;
    __nv_bfloat16 *wth, *wtl, *woth, *wotl;
    cudaGetSymbolAddress((void**)&xh, g_xh);
    cudaGetSymbolAddress((void**)&xl, g_xl);
    cudaGetSymbolAddress((void**)&qh, g_qh);
    cudaGetSymbolAddress((void**)&ql, g_ql);
    cudaGetSymbolAddress((void**)&kh, g_kh);
    cudaGetSymbolAddress((void**)&kl, g_kl);
    cudaGetSymbolAddress((void**)&vh, g_vh);
    cudaGetSymbolAddress((void**)&vl, g_vl);
    cudaGetSymbolAddress((void**)&oh, g_oh);
    cudaGetSymbolAddress((void**)&ol, g_ol);
    cudaGetSymbolAddress((void**)&wth, g_wth);
    cudaGetSymbolAddress((void**)&wtl, g_wtl);
    cudaGetSymbolAddress((void**)&woth, g_woth);
    cudaGetSymbolAddress((void**)&wotl, g_wotl);

    cudaFuncSetAttribute(gemm_tc, cudaFuncAttributeMaxDynamicSharedMemorySize, HT_SMEM);
    cudaFuncSetAttribute(flash_tc, cudaFuncAttributeMaxDynamicSharedMemorySize, FA_SMEM);

    // prep
    split_x_kernel<<<TOKENS * DIM / (256 * 4), 256>>>(x, xh, xl);
    transpose_split_kernel<<<dim3(DIM / 32, INNER / 32), dim3(32, 8)>>>(
        Wq, wth, wtl, DIM, INNER);
    transpose_split_kernel<<<dim3(DIM / 32, 2 * INNER / 32), dim3(32, 8)>>>(
        Wkv, wth + (size_t)INNER * DIM, wtl + (size_t)INNER * DIM, DIM, 2 * INNER);
    transpose_split_kernel<<<dim3(INNER / 32, DIM / 32), dim3(32, 8)>>>(
        Wo, woth, wotl, INNER, DIM);

    // fused [q|k|v] = x @ [Wq|Wkv]  -> bf16 split (q scaled by ATT_SCALE)
    gemm_tc<<<dim3(3 * INNER / 256, TOKENS / 128), 256, HT_SMEM>>>(
        xh, xl, wth, wtl, nullptr, nullptr,
        qh, ql, kh, kl, vh, vl, 3 * INNER, DIM);

    // attention on tensor cores
    flash_tc<<<dim3(SEQ / FA_BQ, BATCH * HEADS), 256, FA_SMEM>>>(
        qh, ql, kh, kl, vh, vl, oh, ol);

    // out = O @ Wo + bo  -> fp32
    gemm_tc<<<dim3(DIM / 256, TOKENS / 128), 256, HT_SMEM>>>(
        oh, ol, woth, wotl, out, bo,
        nullptr, nullptr, nullptr, nullptr, nullptr, nullptr, DIM, INNER);
}

// round 9
// speedup vs baseline: 1.7504x; 1.7504x over previous
#include <cuda_runtime.h>
#include <cuda_fp16.h>
#include <cstdint>

#define BATCH 4
#define SEQ 2048
#define DIM 1024
#define HEADS 16
#define DHEAD 64
#define INNER 1024
#define TOKENS (BATCH * SEQ)
#define ATT_SCALE 0.125f

// ---------------------------------------------------------------------------
// Scratch (allocation-free device globals) — fp16 everywhere.
// Activations kept as hi/lo splits (exact); k, v, weights single fp16.
// ---------------------------------------------------------------------------
__device__ __half g_xh[TOKENS * DIM];
__device__ __half g_xl[TOKENS * DIM];
__device__ __half g_qh[TOKENS * INNER];
__device__ __half g_ql[TOKENS * INNER];
__device__ __half g_kw[TOKENS * INNER];
__device__ __half g_vw[TOKENS * INNER];
__device__ __half g_oh[TOKENS * INNER];
__device__ __half g_ol[TOKENS * INNER];
// fused QKV weight, transposed: rows 0-1023 = Wq^T, 1024-3071 = Wkv^T
__device__ __half g_wt[3 * INNER * DIM];
__device__ __half g_wot[DIM * INNER];

// ---------------------------------------------------------------------------
// Helpers (base-target PTX only: ldmatrix / mma.sync / cp.async)
// ---------------------------------------------------------------------------
__device__ __forceinline__ uint32_t smem_u32(const void* p) {
    uint32_t a;
    asm("{ .reg .u64 t; cvta.to.shared.u64 t, %1; cvt.u32.u64 %0, t; }"
        : "=r"(a) : "l"(p));
    return a;
}

__device__ __forceinline__ void ldm_x4(uint32_t* r, uint32_t addr) {
    asm volatile("ldmatrix.sync.aligned.m8n8.x4.shared.b16 {%0,%1,%2,%3}, [%4];"
                 : "=r"(r[0]), "=r"(r[1]), "=r"(r[2]), "=r"(r[3]) : "r"(addr));
}

__device__ __forceinline__ void ldm_x4_t(uint32_t* r, uint32_t addr) {
    asm volatile("ldmatrix.sync.aligned.m8n8.x4.trans.shared.b16 {%0,%1,%2,%3}, [%4];"
                 : "=r"(r[0]), "=r"(r[1]), "=r"(r[2]), "=r"(r[3]) : "r"(addr));
}

// fp16 inputs, fp32 accumulate
__device__ __forceinline__ void mma16816(float* c, const uint32_t* a, const uint32_t* b) {
    asm volatile(
        "mma.sync.aligned.m16n8k16.row.col.f32.f16.f16.f32 "
        "{%0,%1,%2,%3}, {%4,%5,%6,%7}, {%8,%9}, {%0,%1,%2,%3};"
        : "+f"(c[0]), "+f"(c[1]), "+f"(c[2]), "+f"(c[3])
        : "r"(a[0]), "r"(a[1]), "r"(a[2]), "r"(a[3]), "r"(b[0]), "r"(b[1]));
}

__device__ __forceinline__ void cp_async16(uint32_t saddr, const void* gaddr) {
    asm volatile("cp.async.cg.shared.global [%0], [%1], 16;"
                 :: "r"(saddr), "l"(gaddr) : "memory");
}
__device__ __forceinline__ void cp_commit() {
    asm volatile("cp.async.commit_group;" ::: "memory");
}
template <int N>
__device__ __forceinline__ void cp_wait() {
    asm volatile("cp.async.wait_group %0;" :: "n"(N) : "memory");
}

__device__ __forceinline__ void h_split(float a, __half& h, __half& l) {
    h = __float2half_rn(a);
    l = __float2half_rn(a - __half2float(h));
}

__device__ __forceinline__ void pack_split_h(float x, float y, uint32_t& hi, uint32_t& lo) {
    __half hx = __float2half_rn(x);
    __half hy = __float2half_rn(y);
    __half2 H(hx, hy);
    __half2 L(__float2half_rn(x - __half2float(hx)),
              __float2half_rn(y - __half2float(hy)));
    hi = *(uint32_t*)&H;
    lo = *(uint32_t*)&L;
}

__device__ __forceinline__ uint32_t pack_h2(float x, float y) {
    __half2 H(__float2half_rn(x), __float2half_rn(y));
    return *(uint32_t*)&H;
}

// 128B-row swizzle (flash tiles): 8 x 16B chunks per row, chunk ^= row (mod 8)
#define FSWZ(row, chunk) (((row) << 7) + ((((chunk) ^ (row)) & 7) << 4))
// 64B-row swizzle (gemm tiles): 4 x 16B chunks per row, chunk ^= (row>>1)&3
#define HSWZ(row, chunk) (((row) << 6) + (((chunk) ^ (((row) >> 1) & 3)) << 4))

// ---------------------------------------------------------------------------
// Prep: split x into fp16 hi/lo
// ---------------------------------------------------------------------------
__global__ void split_x_kernel(const float* __restrict__ in,
                               __half* __restrict__ oh,
                               __half* __restrict__ ol) {
    int i = (blockIdx.x * blockDim.x + threadIdx.x) * 4;
    float4 v = *(const float4*)(in + i);
    __half h0, h1, h2, h3, l0, l1, l2, l3;
    h_split(v.x, h0, l0); h_split(v.y, h1, l1);
    h_split(v.z, h2, l2); h_split(v.w, h3, l3);
    *(__half2*)(oh + i)     = __half2(h0, h1);
    *(__half2*)(oh + i + 2) = __half2(h2, h3);
    *(__half2*)(ol + i)     = __half2(l0, l1);
    *(__half2*)(ol + i + 2) = __half2(l2, l3);
}

// ---------------------------------------------------------------------------
// Prep: transpose W[K,N] -> WT[N,K], single fp16
// ---------------------------------------------------------------------------
__global__ void transpose_h_kernel(const float* __restrict__ W,
                                   __half* __restrict__ WT,
                                   int K, int N) {
    __shared__ float t[32][33];
    int k0 = blockIdx.x * 32, n0 = blockIdx.y * 32;
    int x = threadIdx.x, y = threadIdx.y;
#pragma unroll
    for (int j = 0; j < 32; j += 8)
        t[y + j][x] = W[(size_t)(k0 + y + j) * N + n0 + x];
    __syncthreads();
#pragma unroll
    for (int j = 0; j < 32; j += 8)
        WT[(size_t)(n0 + y + j) * K + k0 + x] = __float2half_rn(t[x][y + j]);
}

// ---------------------------------------------------------------------------
// HMMA fp16x2 GEMM:  C[M,N] = (Ah+Al)[M,K] @ BT[N,K]^T  (fp32 accumulate)
// CTA tile 128x128, 512 threads, 16 warps = 4(M) x 4(N), warp tile 32x32.
// 2 MMAs per logical k16 tile (Ah*B + Al*B). k-block 32, 4-stage ring (96 KB).
// Output: fp32 Cf (+bias) if non-null; else QKV epilogue by 1024-col segment:
//   seg0 -> q split fp16 hi/lo scaled by ATT_SCALE; seg1 -> k fp16; seg2 -> v fp16.
// ---------------------------------------------------------------------------
#define HT_TK 32
#define HT_TILE 8192                     // [128 rows][32 fp16] = 8 KB
#define HT_STAGE (3 * HT_TILE)           // Ah/Al/B = 24 KB
#define HT_NSTG 4
#define HT_SMEM (HT_NSTG * HT_STAGE)     // 96 KB

__global__ __launch_bounds__(512)
void gemm_tc(const __half* __restrict__ Ah,
             const __half* __restrict__ Al,
             const __half* __restrict__ Bw,
             float* __restrict__ Cf, const float* __restrict__ bias,
             __half* __restrict__ Qh, __half* __restrict__ Ql,
             __half* __restrict__ Kw, __half* __restrict__ Vw,
             int N, int K)
{
    extern __shared__ char smem[];
    const uint32_t sb = smem_u32(smem);
    const int tid = threadIdx.x;
    const int wid = tid >> 5;
    const int lane = tid & 31;
    const int m0 = blockIdx.y * 128;
    const int n0 = blockIdx.x * 128;
    const int nkb = K / HT_TK;

    const int wm = (wid & 3) * 32;    // warp M offset
    const int wn = (wid >> 2) * 32;   // warp N offset

    // loader: each tile = 128 rows x 4 chunks = 512 chunks; 1 chunk/tile/thread
    const int lrow = tid >> 2;
    const int lch  = tid & 3;
    const uint32_t lsw = HSWZ(lrow, lch);

    auto load_stage = [&](int st, int kb) {
        const uint32_t stg = sb + st * HT_STAGE;
        const size_t kc = (size_t)kb * HT_TK + lch * 8;
        cp_async16(stg + 0 * HT_TILE + lsw, Ah + (size_t)(m0 + lrow) * K + kc);
        cp_async16(stg + 1 * HT_TILE + lsw, Al + (size_t)(m0 + lrow) * K + kc);
        cp_async16(stg + 2 * HT_TILE + lsw, Bw + (size_t)(n0 + lrow) * K + kc);
    };

    float acc[2][4][4];
#pragma unroll
    for (int i = 0; i < 2; i++)
#pragma unroll
        for (int j = 0; j < 4; j++)
#pragma unroll
            for (int e = 0; e < 4; e++) acc[i][j][e] = 0.f;

    const int a_row = lane & 15;
    const int a_chk = lane >> 4;
    const int b_row = (lane & 7) + ((lane >> 4) << 3);
    const int b_chk = (lane >> 3) & 1;

    load_stage(0, 0); cp_commit();
    load_stage(1, 1); cp_commit();
    load_stage(2, 2); cp_commit();

    for (int kb = 0; kb < nkb; kb++) {
        if (kb < nkb - 2)       cp_wait<2>();
        else if (kb == nkb - 2) cp_wait<1>();
        else                    cp_wait<0>();
        __syncthreads();

        if (kb + 3 < nkb) {
            load_stage((kb + 3) & (HT_NSTG - 1), kb + 3);
            cp_commit();
        }

        const uint32_t stg = sb + (kb & (HT_NSTG - 1)) * HT_STAGE;
        const uint32_t sAh = stg;
        const uint32_t sAl = stg + HT_TILE;
        const uint32_t sBw = stg + 2 * HT_TILE;

#pragma unroll
        for (int kk = 0; kk < 2; kk++) {
            uint32_t ah[2][4], al[2][4], bw[2][4];
#pragma unroll
            for (int mt = 0; mt < 2; mt++) {
                int r = wm + mt * 16 + a_row;
                int c = kk * 2 + a_chk;
                ldm_x4(ah[mt], sAh + HSWZ(r, c));
                ldm_x4(al[mt], sAl + HSWZ(r, c));
            }
#pragma unroll
            for (int ng = 0; ng < 2; ng++) {
                int r = wn + ng * 16 + b_row;
                int c = kk * 2 + b_chk;
                ldm_x4(bw[ng], sBw + HSWZ(r, c));
            }
#pragma unroll
            for (int mt = 0; mt < 2; mt++) {
#pragma unroll
                for (int nt = 0; nt < 4; nt++) {
                    const int ng = nt >> 1, hf = (nt & 1) * 2;
                    mma16816(acc[mt][nt], ah[mt], &bw[ng][hf]);
                    mma16816(acc[mt][nt], al[mt], &bw[ng][hf]);
                }
            }
        }
        __syncthreads();
    }

    const int erow = lane >> 2;
    const int ecol = (lane & 3) * 2;

    if (Cf) {
        // fp32 output with bias
#pragma unroll
        for (int mt = 0; mt < 2; mt++) {
#pragma unroll
            for (int nt = 0; nt < 4; nt++) {
                int gcol = n0 + wn + nt * 8 + ecol;
                float b0 = 0.f, b1 = 0.f;
                if (bias) { b0 = bias[gcol]; b1 = bias[gcol + 1]; }
                int r0 = m0 + wm + mt * 16 + erow;
                float2 v0 = make_float2(acc[mt][nt][0] + b0, acc[mt][nt][1] + b1);
                float2 v1 = make_float2(acc[mt][nt][2] + b0, acc[mt][nt][3] + b1);
                *(float2*)(Cf + (size_t)r0 * N + gcol)       = v0;
                *(float2*)(Cf + (size_t)(r0 + 8) * N + gcol) = v1;
            }
        }
    } else {
        const int seg = n0 >> 10;      // 0:q  1:k  2:v
        const int c0 = n0 & 1023;
        if (seg == 0) {
            // q: split fp16 scaled by ATT_SCALE
#pragma unroll
            for (int mt = 0; mt < 2; mt++) {
#pragma unroll
                for (int nt = 0; nt < 4; nt++) {
                    int r0 = m0 + wm + mt * 16 + erow;
                    int lcol = c0 + wn + nt * 8 + ecol;
                    uint32_t h0, l0h, h1, l1h;
                    pack_split_h(acc[mt][nt][0] * ATT_SCALE, acc[mt][nt][1] * ATT_SCALE, h0, l0h);
                    pack_split_h(acc[mt][nt][2] * ATT_SCALE, acc[mt][nt][3] * ATT_SCALE, h1, l1h);
                    *(uint32_t*)(Qh + (size_t)r0 * 1024 + lcol)       = h0;
                    *(uint32_t*)(Ql + (size_t)r0 * 1024 + lcol)       = l0h;
                    *(uint32_t*)(Qh + (size_t)(r0 + 8) * 1024 + lcol) = h1;
                    *(uint32_t*)(Ql + (size_t)(r0 + 8) * 1024 + lcol) = l1h;
                }
            }
        } else {
            __half* D = (seg == 1) ? Kw : Vw;
#pragma unroll
            for (int mt = 0; mt < 2; mt++) {
#pragma unroll
                for (int nt = 0; nt < 4; nt++) {
                    int r0 = m0 + wm + mt * 16 + erow;
                    int lcol = c0 + wn + nt * 8 + ecol;
                    *(uint32_t*)(D + (size_t)r0 * 1024 + lcol) =
                        pack_h2(acc[mt][nt][0], acc[mt][nt][1]);
                    *(uint32_t*)(D + (size_t)(r0 + 8) * 1024 + lcol) =
                        pack_h2(acc[mt][nt][2], acc[mt][nt][3]);
                }
            }
        }
    }
}

// ---------------------------------------------------------------------------
// Flash attention on mma.sync, fp16x2: S = (Qh+Ql)·K^T, O = (Ph+Pl)·V.
// CTA = 128 q rows x one (b,h). 8 warps, 16 rows each. K-chunks of 64,
// 3-stage cp.async KV ring (K 8KB + V 8KB per stage). smem = 32+48 = 80 KB.
// ---------------------------------------------------------------------------
#define FA_BQ 128
#define FA_BK 64
#define FA_NC (SEQ / FA_BK)
#define FA_KVST 16384
#define FA_SMEM (32768 + 3 * FA_KVST)

__global__ __launch_bounds__(256, 1)
void flash_tc(const __half* __restrict__ Qh, const __half* __restrict__ Ql,
              const __half* __restrict__ Kw, const __half* __restrict__ Vw,
              __half* __restrict__ Oh, __half* __restrict__ Ol)
{
    extern __shared__ char smem[];
    const uint32_t sb = smem_u32(smem);
    const int tid = threadIdx.x;
    const int wid = tid >> 5;
    const int lane = tid & 31;
    const int qt = blockIdx.x;
    const int b  = blockIdx.y >> 4;
    const int h  = blockIdx.y & 15;

    const size_t base_q  = (size_t)(b * SEQ + qt * FA_BQ) * INNER + h * DHEAD;
    const size_t base_kv = (size_t)b * SEQ * INNER + h * DHEAD;

    // ---- Q load (split, 2 x 16KB) ----
    {
        int row = tid >> 3, chunk = tid & 7;
#pragma unroll
        for (int p = 0; p < 4; p++) {
            int r = row + p * 32;
            size_t go = base_q + (size_t)r * INNER + chunk * 8;
            cp_async16(sb +         FSWZ(r, chunk), Qh + go);
            cp_async16(sb + 16384 + FSWZ(r, chunk), Ql + go);
        }
    }
    auto load_kv = [&](int st, int kc) {
        const uint32_t stg = sb + 32768 + st * FA_KVST;
        int row = tid >> 3, chunk = tid & 7;
        size_t gk = base_kv + (size_t)(kc * FA_BK) * INNER + chunk * 8;
#pragma unroll
        for (int p = 0; p < 2; p++) {
            int r = row + p * 32;
            size_t go = gk + (size_t)r * INNER;
            cp_async16(stg +        FSWZ(r, chunk), Kw + go);
            cp_async16(stg + 8192 + FSWZ(r, chunk), Vw + go);
        }
    };
    load_kv(0, 0); cp_commit();
    load_kv(1, 1); cp_commit();

    uint32_t qfh[4][4], qfl[4][4];
    float oacc[8][4];
#pragma unroll
    for (int j = 0; j < 8; j++)
#pragma unroll
        for (int e = 0; e < 4; e++) oacc[j][e] = 0.f;
    float m0 = -1e30f, m1 = -1e30f, l0 = 0.f, l1 = 0.f;

    for (int kc = 0; kc < FA_NC; kc++) {
        if (kc + 1 < FA_NC) cp_wait<1>(); else cp_wait<0>();
        __syncthreads();

        if (kc == 0) {
#pragma unroll
            for (int kk = 0; kk < 4; kk++) {
                int r = wid * 16 + (lane & 15);
                int c = 2 * kk + (lane >> 4);
                ldm_x4(qfh[kk], sb +         FSWZ(r, c));
                ldm_x4(qfl[kk], sb + 16384 + FSWZ(r, c));
            }
        }
        const uint32_t stg = sb + 32768 + (kc % 3) * FA_KVST;

        // ---- S = Q @ K^T (fp16x2) ----
        float sacc[8][4];
#pragma unroll
        for (int t = 0; t < 8; t++)
#pragma unroll
            for (int e = 0; e < 4; e++) sacc[t][e] = 0.f;
#pragma unroll
        for (int kk = 0; kk < 4; kk++) {
            uint32_t kb[4][4];
#pragma unroll
            for (int G = 0; G < 4; G++) {
                int r = 16 * G + ((lane >> 4) << 3) + (lane & 7);
                int c = 2 * kk + ((lane >> 3) & 1);
                ldm_x4(kb[G], stg + FSWZ(r, c));
            }
#pragma unroll
            for (int t = 0; t < 8; t++) {
                const int G = t >> 1, hf = (t & 1) * 2;
                mma16816(sacc[t], qfh[kk], &kb[G][hf]);
                mma16816(sacc[t], qfl[kk], &kb[G][hf]);
            }
        }

        // ---- online softmax ----
        float mx0 = -1e30f, mx1 = -1e30f;
#pragma unroll
        for (int t = 0; t < 8; t++) {
            mx0 = fmaxf(mx0, fmaxf(sacc[t][0], sacc[t][1]));
            mx1 = fmaxf(mx1, fmaxf(sacc[t][2], sacc[t][3]));
        }
        mx0 = fmaxf(mx0, __shfl_xor_sync(0xffffffffu, mx0, 1));
        mx0 = fmaxf(mx0, __shfl_xor_sync(0xffffffffu, mx0, 2));
        mx1 = fmaxf(mx1, __shfl_xor_sync(0xffffffffu, mx1, 1));
        mx1 = fmaxf(mx1, __shfl_xor_sync(0xffffffffu, mx1, 2));
        float mn0 = fmaxf(m0, mx0), mn1 = fmaxf(m1, mx1);
        float a0 = __expf(m0 - mn0), a1 = __expf(m1 - mn1);
        m0 = mn0; m1 = mn1;
        float s0 = 0.f, s1 = 0.f;
#pragma unroll
        for (int t = 0; t < 8; t++) {
            sacc[t][0] = __expf(sacc[t][0] - mn0); s0 += sacc[t][0];
            sacc[t][1] = __expf(sacc[t][1] - mn0); s0 += sacc[t][1];
            sacc[t][2] = __expf(sacc[t][2] - mn1); s1 += sacc[t][2];
            sacc[t][3] = __expf(sacc[t][3] - mn1); s1 += sacc[t][3];
        }
        s0 += __shfl_xor_sync(0xffffffffu, s0, 1);
        s0 += __shfl_xor_sync(0xffffffffu, s0, 2);
        s1 += __shfl_xor_sync(0xffffffffu, s1, 1);
        s1 += __shfl_xor_sync(0xffffffffu, s1, 2);
        l0 = l0 * a0 + s0;
        l1 = l1 * a1 + s1;
#pragma unroll
        for (int j = 0; j < 8; j++) {
            oacc[j][0] *= a0; oacc[j][1] *= a0;
            oacc[j][2] *= a1; oacc[j][3] *= a1;
        }

        // ---- O += P @ V (fp16x2), P split in registers ----
#pragma unroll
        for (int s = 0; s < 4; s++) {
            uint32_t ph[4], pl[4];
            pack_split_h(sacc[2 * s][0],     sacc[2 * s][1],     ph[0], pl[0]);
            pack_split_h(sacc[2 * s][2],     sacc[2 * s][3],     ph[1], pl[1]);
            pack_split_h(sacc[2 * s + 1][0], sacc[2 * s + 1][1], ph[2], pl[2]);
            pack_split_h(sacc[2 * s + 1][2], sacc[2 * s + 1][3], ph[3], pl[3]);
            uint32_t vb[4][4];
#pragma unroll
            for (int J = 0; J < 4; J++) {
                int r = 16 * s + (lane & 7) + ((lane >> 3) & 1) * 8;
                int c = 2 * J + (lane >> 4);
                ldm_x4_t(vb[J], stg + 8192 + FSWZ(r, c));
            }
#pragma unroll
            for (int j = 0; j < 8; j++) {
                const int J = j >> 1, hf = (j & 1) * 2;
                mma16816(oacc[j], ph, &vb[J][hf]);
                mma16816(oacc[j], pl, &vb[J][hf]);
            }
        }

        if (kc + 2 < FA_NC) {
            load_kv((kc + 2) % 3, kc + 2);
            cp_commit();
        }
    }

    // ---- normalize + write O (fp16 hi/lo split) ----
    float inv0 = 1.f / l0, inv1 = 1.f / l1;
    int r = lane >> 2;
    size_t row0 = (size_t)(b * SEQ + qt * FA_BQ + wid * 16 + r);
    size_t row1 = row0 + 8;
    int colb = h * DHEAD + (lane & 3) * 2;
#pragma unroll
    for (int j = 0; j < 8; j++) {
        size_t o0 = row0 * INNER + colb + j * 8;
        size_t o1 = row1 * INNER + colb + j * 8;
        uint32_t h0, lo0, h1, lo1;
        pack_split_h(oacc[j][0] * inv0, oacc[j][1] * inv0, h0, lo0);
        pack_split_h(oacc[j][2] * inv1, oacc[j][3] * inv1, h1, lo1);
        *(uint32_t*)(Oh + o0) = h0;
        *(uint32_t*)(Ol + o0) = lo0;
        *(uint32_t*)(Oh + o1) = h1;
        *(uint32_t*)(Ol + o1) = lo1;
    }
}

// ---------------------------------------------------------------------------
extern "C" void kernel_launch(void* const* d_in, const int* in_sizes, int n_in,
                              void* d_out, int out_size)
{
    const float* x   = (const float*)d_in[0];
    const float* Wq  = (const float*)d_in[1];
    const float* Wkv = (const float*)d_in[2];
    const float* Wo  = (const float*)d_in[3];
    const float* bo  = (const float*)d_in[4];
    float* out = (float*)d_out;

    __half *xh, *xl, *qh, *ql, *kw, *vw, *oh, *ol, *wt, *wot;
    cudaGetSymbolAddress((void**)&xh, g_xh);
    cudaGetSymbolAddress((void**)&xl, g_xl);
    cudaGetSymbolAddress((void**)&qh, g_qh);
    cudaGetSymbolAddress((void**)&ql, g_ql);
    cudaGetSymbolAddress((void**)&kw, g_kw);
    cudaGetSymbolAddress((void**)&vw, g_vw);
    cudaGetSymbolAddress((void**)&oh, g_oh);
    cudaGetSymbolAddress((void**)&ol, g_ol);
    cudaGetSymbolAddress((void**)&wt, g_wt);
    cudaGetSymbolAddress((void**)&wot, g_wot);

    cudaFuncSetAttribute(gemm_tc, cudaFuncAttributeMaxDynamicSharedMemorySize, HT_SMEM);
    cudaFuncSetAttribute(flash_tc, cudaFuncAttributeMaxDynamicSharedMemorySize, FA_SMEM);

    // prep: split x; transpose Wq/Wkv into fused [3072,1024] fp16 + Wo^T fp16
    split_x_kernel<<<TOKENS * DIM / (256 * 4), 256>>>(x, xh, xl);
    transpose_h_kernel<<<dim3(DIM / 32, INNER / 32), dim3(32, 8)>>>(
        Wq, wt, DIM, INNER);
    transpose_h_kernel<<<dim3(DIM / 32, 2 * INNER / 32), dim3(32, 8)>>>(
        Wkv, wt + (size_t)INNER * DIM, DIM, 2 * INNER);
    transpose_h_kernel<<<dim3(INNER / 32, DIM / 32), dim3(32, 8)>>>(
        Wo, wot, INNER, DIM);

    // fused [q|k|v] = x @ [Wq|Wkv]  (q split+scaled, k/v single fp16)
    gemm_tc<<<dim3(3 * INNER / 128, TOKENS / 128), 512, HT_SMEM>>>(
        xh, xl, wt, nullptr, nullptr, qh, ql, kw, vw, 3 * INNER, DIM);

    // attention on tensor cores
    flash_tc<<<dim3(SEQ / FA_BQ, BATCH * HEADS), 256, FA_SMEM>>>(
        qh, ql, kw, vw, oh, ol);

    // out = O @ Wo + bo  -> fp32
    gemm_tc<<<dim3(DIM / 128, TOKENS / 128), 512, HT_SMEM>>>(
        oh, ol, wot, out, bo, nullptr, nullptr, nullptr, nullptr, DIM, INNER);
}

// round 10
// speedup vs baseline: 2.2603x; 1.2914x over previous
#include <cuda_runtime.h>
#include <cuda_fp16.h>
#include <cstdint>

#define BATCH 4
#define SEQ 2048
#define DIM 1024
#define HEADS 16
#define DHEAD 64
#define INNER 1024
#define TOKENS (BATCH * SEQ)
#define ATT_SCALE 0.125f

// ---------------------------------------------------------------------------
// Scratch (allocation-free device globals) — fp16.
// x kept as exact hi/lo split; q, k, v, O, weights single fp16.
// ---------------------------------------------------------------------------
__device__ __half g_xh[TOKENS * DIM];
__device__ __half g_xl[TOKENS * DIM];
__device__ __half g_qw[TOKENS * INNER];
__device__ __half g_kw[TOKENS * INNER];
__device__ __half g_vw[TOKENS * INNER];
__device__ __half g_ow[TOKENS * INNER];
// fused QKV weight, transposed: rows 0-1023 = Wq^T, 1024-3071 = Wkv^T
__device__ __half g_wt[3 * INNER * DIM];
__device__ __half g_wot[DIM * INNER];

// ---------------------------------------------------------------------------
// Helpers (base-target PTX only: ldmatrix / mma.sync / cp.async)
// ---------------------------------------------------------------------------
__device__ __forceinline__ uint32_t smem_u32(const void* p) {
    uint32_t a;
    asm("{ .reg .u64 t; cvta.to.shared.u64 t, %1; cvt.u32.u64 %0, t; }"
        : "=r"(a) : "l"(p));
    return a;
}

__device__ __forceinline__ void ldm_x4(uint32_t* r, uint32_t addr) {
    asm volatile("ldmatrix.sync.aligned.m8n8.x4.shared.b16 {%0,%1,%2,%3}, [%4];"
                 : "=r"(r[0]), "=r"(r[1]), "=r"(r[2]), "=r"(r[3]) : "r"(addr));
}

__device__ __forceinline__ void ldm_x4_t(uint32_t* r, uint32_t addr) {
    asm volatile("ldmatrix.sync.aligned.m8n8.x4.trans.shared.b16 {%0,%1,%2,%3}, [%4];"
                 : "=r"(r[0]), "=r"(r[1]), "=r"(r[2]), "=r"(r[3]) : "r"(addr));
}

// fp16 inputs, fp32 accumulate
__device__ __forceinline__ void mma16816(float* c, const uint32_t* a, const uint32_t* b) {
    asm volatile(
        "mma.sync.aligned.m16n8k16.row.col.f32.f16.f16.f32 "
        "{%0,%1,%2,%3}, {%4,%5,%6,%7}, {%8,%9}, {%0,%1,%2,%3};"
        : "+f"(c[0]), "+f"(c[1]), "+f"(c[2]), "+f"(c[3])
        : "r"(a[0]), "r"(a[1]), "r"(a[2]), "r"(a[3]), "r"(b[0]), "r"(b[1]));
}

__device__ __forceinline__ void cp_async16(uint32_t saddr, const void* gaddr) {
    asm volatile("cp.async.cg.shared.global [%0], [%1], 16;"
                 :: "r"(saddr), "l"(gaddr) : "memory");
}
__device__ __forceinline__ void cp_commit() {
    asm volatile("cp.async.commit_group;" ::: "memory");
}
template <int N>
__device__ __forceinline__ void cp_wait() {
    asm volatile("cp.async.wait_group %0;" :: "n"(N) : "memory");
}

__device__ __forceinline__ void h_split(float a, __half& h, __half& l) {
    h = __float2half_rn(a);
    l = __float2half_rn(a - __half2float(h));
}

__device__ __forceinline__ uint32_t pack_h2(float x, float y) {
    __half2 H(__float2half_rn(x), __float2half_rn(y));
    return *(uint32_t*)&H;
}

// 128B-row swizzle (flash tiles): 8 x 16B chunks per row, chunk ^= row (mod 8)
#define FSWZ(row, chunk) (((row) << 7) + ((((chunk) ^ (row)) & 7) << 4))
// 64B-row swizzle (gemm tiles): 4 x 16B chunks per row, chunk ^= (row>>1)&3
#define HSWZ(row, chunk) (((row) << 6) + (((chunk) ^ (((row) >> 1) & 3)) << 4))

// ---------------------------------------------------------------------------
// Prep: split x into fp16 hi/lo
// ---------------------------------------------------------------------------
__global__ void split_x_kernel(const float* __restrict__ in,
                               __half* __restrict__ oh,
                               __half* __restrict__ ol) {
    int i = (blockIdx.x * blockDim.x + threadIdx.x) * 4;
    float4 v = *(const float4*)(in + i);
    __half h0, h1, h2, h3, l0, l1, l2, l3;
    h_split(v.x, h0, l0); h_split(v.y, h1, l1);
    h_split(v.z, h2, l2); h_split(v.w, h3, l3);
    *(__half2*)(oh + i)     = __half2(h0, h1);
    *(__half2*)(oh + i + 2) = __half2(h2, h3);
    *(__half2*)(ol + i)     = __half2(l0, l1);
    *(__half2*)(ol + i + 2) = __half2(l2, l3);
}

// ---------------------------------------------------------------------------
// Prep: transpose W[K,N] -> WT[N,K], single fp16
// ---------------------------------------------------------------------------
__global__ void transpose_h_kernel(const float* __restrict__ W,
                                   __half* __restrict__ WT,
                                   int K, int N) {
    __shared__ float t[32][33];
    int k0 = blockIdx.x * 32, n0 = blockIdx.y * 32;
    int x = threadIdx.x, y = threadIdx.y;
#pragma unroll
    for (int j = 0; j < 32; j += 8)
        t[y + j][x] = W[(size_t)(k0 + y + j) * N + n0 + x];
    __syncthreads();
#pragma unroll
    for (int j = 0; j < 32; j += 8)
        WT[(size_t)(n0 + y + j) * K + k0 + x] = __float2half_rn(t[x][y + j]);
}

// ---------------------------------------------------------------------------
// HMMA GEMM:  C[M,N] = A[M,K] @ BT[N,K]^T  (fp32 accumulate)
// SPLIT_A: A = Ah + Al (2 MMAs / tile); else A = Ah (1 MMA / tile).
// CTA tile 128x128, 512 threads, 16 warps = 4(M) x 4(N), warp tile 32x32.
// k-block 32, 4-stage cp.async ring. One sync per k-block.
// Output: fp32 Cf (+bias) if non-null; else QKV epilogue by 1024-col segment:
//   seg0 -> q fp16 scaled by ATT_SCALE; seg1 -> k fp16; seg2 -> v fp16.
// ---------------------------------------------------------------------------
#define HT_TK 32
#define HT_TILE 8192                     // [128 rows][32 fp16] = 8 KB
#define HT_NSTG 4

template <bool SPLIT_A>
__global__ __launch_bounds__(512)
void gemm_tc(const __half* __restrict__ Ah,
             const __half* __restrict__ Al,
             const __half* __restrict__ Bw,
             float* __restrict__ Cf, const float* __restrict__ bias,
             __half* __restrict__ Sq, __half* __restrict__ Sk,
             __half* __restrict__ Sv,
             int N, int K)
{
    constexpr int NT = SPLIT_A ? 3 : 2;          // tiles per stage
    constexpr int STAGE = NT * HT_TILE;
    extern __shared__ char smem[];
    const uint32_t sb = smem_u32(smem);
    const int tid = threadIdx.x;
    const int wid = tid >> 5;
    const int lane = tid & 31;
    const int m0 = blockIdx.y * 128;
    const int n0 = blockIdx.x * 128;
    const int nkb = K / HT_TK;

    const int wm = (wid & 3) * 32;
    const int wn = (wid >> 2) * 32;

    const int lrow = tid >> 2;
    const int lch  = tid & 3;
    const uint32_t lsw = HSWZ(lrow, lch);

    auto load_stage = [&](int st, int kb) {
        const uint32_t stg = sb + st * STAGE;
        const size_t kc = (size_t)kb * HT_TK + lch * 8;
        cp_async16(stg + lsw, Ah + (size_t)(m0 + lrow) * K + kc);
        if (SPLIT_A)
            cp_async16(stg + HT_TILE + lsw, Al + (size_t)(m0 + lrow) * K + kc);
        cp_async16(stg + (NT - 1) * HT_TILE + lsw, Bw + (size_t)(n0 + lrow) * K + kc);
    };

    float acc[2][4][4];
#pragma unroll
    for (int i = 0; i < 2; i++)
#pragma unroll
        for (int j = 0; j < 4; j++)
#pragma unroll
            for (int e = 0; e < 4; e++) acc[i][j][e] = 0.f;

    const int a_row = lane & 15;
    const int a_chk = lane >> 4;
    const int b_row = (lane & 7) + ((lane >> 4) << 3);
    const int b_chk = (lane >> 3) & 1;

    load_stage(0, 0); cp_commit();
    load_stage(1, 1); cp_commit();
    load_stage(2, 2); cp_commit();

    for (int kb = 0; kb < nkb; kb++) {
        if (kb < nkb - 2)       cp_wait<2>();
        else if (kb == nkb - 2) cp_wait<1>();
        else                    cp_wait<0>();
        __syncthreads();

        if (kb + 3 < nkb) {
            load_stage((kb + 3) & (HT_NSTG - 1), kb + 3);
            cp_commit();
        }

        const uint32_t stg = sb + (kb & (HT_NSTG - 1)) * STAGE;
        const uint32_t sAh = stg;
        const uint32_t sAl = stg + HT_TILE;
        const uint32_t sBw = stg + (NT - 1) * HT_TILE;

#pragma unroll
        for (int kk = 0; kk < 2; kk++) {
            uint32_t ah[2][4], al[2][4], bw[2][4];
#pragma unroll
            for (int mt = 0; mt < 2; mt++) {
                int r = wm + mt * 16 + a_row;
                int c = kk * 2 + a_chk;
                ldm_x4(ah[mt], sAh + HSWZ(r, c));
                if (SPLIT_A) ldm_x4(al[mt], sAl + HSWZ(r, c));
            }
#pragma unroll
            for (int ng = 0; ng < 2; ng++) {
                int r = wn + ng * 16 + b_row;
                int c = kk * 2 + b_chk;
                ldm_x4(bw[ng], sBw + HSWZ(r, c));
            }
#pragma unroll
            for (int mt = 0; mt < 2; mt++) {
#pragma unroll
                for (int nt = 0; nt < 4; nt++) {
                    const int ng = nt >> 1, hf = (nt & 1) * 2;
                    mma16816(acc[mt][nt], ah[mt], &bw[ng][hf]);
                    if (SPLIT_A) mma16816(acc[mt][nt], al[mt], &bw[ng][hf]);
                }
            }
        }
        __syncthreads();
    }

    const int erow = lane >> 2;
    const int ecol = (lane & 3) * 2;

    if (Cf) {
        // fp32 output with bias
#pragma unroll
        for (int mt = 0; mt < 2; mt++) {
#pragma unroll
            for (int nt = 0; nt < 4; nt++) {
                int gcol = n0 + wn + nt * 8 + ecol;
                float b0 = 0.f, b1 = 0.f;
                if (bias) { b0 = bias[gcol]; b1 = bias[gcol + 1]; }
                int r0 = m0 + wm + mt * 16 + erow;
                float2 v0 = make_float2(acc[mt][nt][0] + b0, acc[mt][nt][1] + b1);
                float2 v1 = make_float2(acc[mt][nt][2] + b0, acc[mt][nt][3] + b1);
                *(float2*)(Cf + (size_t)r0 * N + gcol)       = v0;
                *(float2*)(Cf + (size_t)(r0 + 8) * N + gcol) = v1;
            }
        }
    } else {
        const int seg = n0 >> 10;      // 0:q  1:k  2:v
        const int c0 = n0 & 1023;
        const float sc = (seg == 0) ? ATT_SCALE : 1.0f;
        __half* D = (seg == 0) ? Sq : (seg == 1) ? Sk : Sv;
#pragma unroll
        for (int mt = 0; mt < 2; mt++) {
#pragma unroll
            for (int nt = 0; nt < 4; nt++) {
                int r0 = m0 + wm + mt * 16 + erow;
                int lcol = c0 + wn + nt * 8 + ecol;
                *(uint32_t*)(D + (size_t)r0 * 1024 + lcol) =
                    pack_h2(acc[mt][nt][0] * sc, acc[mt][nt][1] * sc);
                *(uint32_t*)(D + (size_t)(r0 + 8) * 1024 + lcol) =
                    pack_h2(acc[mt][nt][2] * sc, acc[mt][nt][3] * sc);
            }
        }
    }
}

// ---------------------------------------------------------------------------
// Flash attention on mma.sync, single fp16 Q/K/V/P (fp32 accumulate).
// CTA = 128 q rows x one (b,h). 8 warps, 16 rows each. K-chunks of 64,
// 3-stage cp.async KV ring. smem = 16 + 48 = 64 KB -> 2 CTAs/SM.
// ---------------------------------------------------------------------------
#define FA_BQ 128
#define FA_BK 64
#define FA_NC (SEQ / FA_BK)
#define FA_KVST 16384
#define FA_SMEM (16384 + 3 * FA_KVST)

__global__ __launch_bounds__(256, 2)
void flash_tc(const __half* __restrict__ Qw,
              const __half* __restrict__ Kw, const __half* __restrict__ Vw,
              __half* __restrict__ Ow)
{
    extern __shared__ char smem[];
    const uint32_t sb = smem_u32(smem);
    const int tid = threadIdx.x;
    const int wid = tid >> 5;
    const int lane = tid & 31;
    const int qt = blockIdx.x;
    const int b  = blockIdx.y >> 4;
    const int h  = blockIdx.y & 15;

    const size_t base_q  = (size_t)(b * SEQ + qt * FA_BQ) * INNER + h * DHEAD;
    const size_t base_kv = (size_t)b * SEQ * INNER + h * DHEAD;

    // ---- Q load (single, 16 KB) ----
    {
        int row = tid >> 3, chunk = tid & 7;
#pragma unroll
        for (int p = 0; p < 4; p++) {
            int r = row + p * 32;
            cp_async16(sb + FSWZ(r, chunk), Qw + base_q + (size_t)r * INNER + chunk * 8);
        }
    }
    auto load_kv = [&](int st, int kc) {
        const uint32_t stg = sb + 16384 + st * FA_KVST;
        int row = tid >> 3, chunk = tid & 7;
        size_t gk = base_kv + (size_t)(kc * FA_BK) * INNER + chunk * 8;
#pragma unroll
        for (int p = 0; p < 2; p++) {
            int r = row + p * 32;
            size_t go = gk + (size_t)r * INNER;
            cp_async16(stg +        FSWZ(r, chunk), Kw + go);
            cp_async16(stg + 8192 + FSWZ(r, chunk), Vw + go);
        }
    };
    load_kv(0, 0); cp_commit();
    load_kv(1, 1); cp_commit();

    uint32_t qf[4][4];
    float oacc[8][4];
#pragma unroll
    for (int j = 0; j < 8; j++)
#pragma unroll
        for (int e = 0; e < 4; e++) oacc[j][e] = 0.f;
    float m0 = -1e30f, m1 = -1e30f, l0 = 0.f, l1 = 0.f;

    for (int kc = 0; kc < FA_NC; kc++) {
        if (kc + 1 < FA_NC) cp_wait<1>(); else cp_wait<0>();
        __syncthreads();

        if (kc == 0) {
#pragma unroll
            for (int kk = 0; kk < 4; kk++) {
                int r = wid * 16 + (lane & 15);
                int c = 2 * kk + (lane >> 4);
                ldm_x4(qf[kk], sb + FSWZ(r, c));
            }
        }
        const uint32_t stg = sb + 16384 + (kc % 3) * FA_KVST;

        // ---- S = Q @ K^T ----
        float sacc[8][4];
#pragma unroll
        for (int t = 0; t < 8; t++)
#pragma unroll
            for (int e = 0; e < 4; e++) sacc[t][e] = 0.f;
#pragma unroll
        for (int kk = 0; kk < 4; kk++) {
            uint32_t kb[4][4];
#pragma unroll
            for (int G = 0; G < 4; G++) {
                int r = 16 * G + ((lane >> 4) << 3) + (lane & 7);
                int c = 2 * kk + ((lane >> 3) & 1);
                ldm_x4(kb[G], stg + FSWZ(r, c));
            }
#pragma unroll
            for (int t = 0; t < 8; t++)
                mma16816(sacc[t], qf[kk], &kb[t >> 1][(t & 1) * 2]);
        }

        // ---- online softmax ----
        float mx0 = -1e30f, mx1 = -1e30f;
#pragma unroll
        for (int t = 0; t < 8; t++) {
            mx0 = fmaxf(mx0, fmaxf(sacc[t][0], sacc[t][1]));
            mx1 = fmaxf(mx1, fmaxf(sacc[t][2], sacc[t][3]));
        }
        mx0 = fmaxf(mx0, __shfl_xor_sync(0xffffffffu, mx0, 1));
        mx0 = fmaxf(mx0, __shfl_xor_sync(0xffffffffu, mx0, 2));
        mx1 = fmaxf(mx1, __shfl_xor_sync(0xffffffffu, mx1, 1));
        mx1 = fmaxf(mx1, __shfl_xor_sync(0xffffffffu, mx1, 2));
        float mn0 = fmaxf(m0, mx0), mn1 = fmaxf(m1, mx1);
        float a0 = __expf(m0 - mn0), a1 = __expf(m1 - mn1);
        m0 = mn0; m1 = mn1;
        float s0 = 0.f, s1 = 0.f;
#pragma unroll
        for (int t = 0; t < 8; t++) {
            sacc[t][0] = __expf(sacc[t][0] - mn0); s0 += sacc[t][0];
            sacc[t][1] = __expf(sacc[t][1] - mn0); s0 += sacc[t][1];
            sacc[t][2] = __expf(sacc[t][2] - mn1); s1 += sacc[t][2];
            sacc[t][3] = __expf(sacc[t][3] - mn1); s1 += sacc[t][3];
        }
        s0 += __shfl_xor_sync(0xffffffffu, s0, 1);
        s0 += __shfl_xor_sync(0xffffffffu, s0, 2);
        s1 += __shfl_xor_sync(0xffffffffu, s1, 1);
        s1 += __shfl_xor_sync(0xffffffffu, s1, 2);
        l0 = l0 * a0 + s0;
        l1 = l1 * a1 + s1;
#pragma unroll
        for (int j = 0; j < 8; j++) {
            oacc[j][0] *= a0; oacc[j][1] *= a0;
            oacc[j][2] *= a1; oacc[j][3] *= a1;
        }

        // ---- O += P @ V (P single fp16) ----
#pragma unroll
        for (int s = 0; s < 4; s++) {
            uint32_t ph[4];
            ph[0] = pack_h2(sacc[2 * s][0],     sacc[2 * s][1]);
            ph[1] = pack_h2(sacc[2 * s][2],     sacc[2 * s][3]);
            ph[2] = pack_h2(sacc[2 * s + 1][0], sacc[2 * s + 1][1]);
            ph[3] = pack_h2(sacc[2 * s + 1][2], sacc[2 * s + 1][3]);
            uint32_t vb[4][4];
#pragma unroll
            for (int J = 0; J < 4; J++) {
                int r = 16 * s + (lane & 7) + ((lane >> 3) & 1) * 8;
                int c = 2 * J + (lane >> 4);
                ldm_x4_t(vb[J], stg + 8192 + FSWZ(r, c));
            }
#pragma unroll
            for (int j = 0; j < 8; j++)
                mma16816(oacc[j], ph, &vb[j >> 1][(j & 1) * 2]);
        }

        if (kc + 2 < FA_NC) {
            load_kv((kc + 2) % 3, kc + 2);
            cp_commit();
        }
    }

    // ---- normalize + write O (single fp16) ----
    float inv0 = 1.f / l0, inv1 = 1.f / l1;
    int r = lane >> 2;
    size_t row0 = (size_t)(b * SEQ + qt * FA_BQ + wid * 16 + r);
    size_t row1 = row0 + 8;
    int colb = h * DHEAD + (lane & 3) * 2;
#pragma unroll
    for (int j = 0; j < 8; j++) {
        *(uint32_t*)(Ow + row0 * INNER + colb + j * 8) =
            pack_h2(oacc[j][0] * inv0, oacc[j][1] * inv0);
        *(uint32_t*)(Ow + row1 * INNER + colb + j * 8) =
            pack_h2(oacc[j][2] * inv1, oacc[j][3] * inv1);
    }
}

// ---------------------------------------------------------------------------
extern "C" void kernel_launch(void* const* d_in, const int* in_sizes, int n_in,
                              void* d_out, int out_size)
{
    const float* x   = (const float*)d_in[0];
    const float* Wq  = (const float*)d_in[1];
    const float* Wkv = (const float*)d_in[2];
    const float* Wo  = (const float*)d_in[3];
    const float* bo  = (const float*)d_in[4];
    float* out = (float*)d_out;

    __half *xh, *xl, *qw, *kw, *vw, *ow, *wt, *wot;
    cudaGetSymbolAddress((void**)&xh, g_xh);
    cudaGetSymbolAddress((void**)&xl, g_xl);
    cudaGetSymbolAddress((void**)&qw, g_qw);
    cudaGetSymbolAddress((void**)&kw, g_kw);
    cudaGetSymbolAddress((void**)&vw, g_vw);
    cudaGetSymbolAddress((void**)&ow, g_ow);
    cudaGetSymbolAddress((void**)&wt, g_wt);
    cudaGetSymbolAddress((void**)&wot, g_wot);

    cudaFuncSetAttribute(gemm_tc<true>,  cudaFuncAttributeMaxDynamicSharedMemorySize,
                         HT_NSTG * 3 * HT_TILE);
    cudaFuncSetAttribute(gemm_tc<false>, cudaFuncAttributeMaxDynamicSharedMemorySize,
                         HT_NSTG * 2 * HT_TILE);
    cudaFuncSetAttribute(flash_tc, cudaFuncAttributeMaxDynamicSharedMemorySize, FA_SMEM);

    // prep: split x; transpose Wq/Wkv into fused [3072,1024] fp16 + Wo^T fp16
    split_x_kernel<<<TOKENS * DIM / (256 * 4), 256>>>(x, xh, xl);
    transpose_h_kernel<<<dim3(DIM / 32, INNER / 32), dim3(32, 8)>>>(
        Wq, wt, DIM, INNER);
    transpose_h_kernel<<<dim3(DIM / 32, 2 * INNER / 32), dim3(32, 8)>>>(
        Wkv, wt + (size_t)INNER * DIM, DIM, 2 * INNER);
    transpose_h_kernel<<<dim3(INNER / 32, DIM / 32), dim3(32, 8)>>>(
        Wo, wot, INNER, DIM);

    // fused [q|k|v] = (xh+xl) @ [Wq|Wkv]  (q scaled; all single fp16 out)
    gemm_tc<true><<<dim3(3 * INNER / 128, TOKENS / 128), 512, HT_NSTG * 3 * HT_TILE>>>(
        xh, xl, wt, nullptr, nullptr, qw, kw, vw, 3 * INNER, DIM);

    // attention on tensor cores
    flash_tc<<<dim3(SEQ / FA_BQ, BATCH * HEADS), 256, FA_SMEM>>>(qw, kw, vw, ow);

    // out = O @ Wo + bo  -> fp32
    gemm_tc<false><<<dim3(DIM / 128, TOKENS / 128), 512, HT_NSTG * 2 * HT_TILE>>>(
        ow, nullptr, wot, out, bo, nullptr, nullptr, nullptr, DIM, INNER);
}

// round 11
// speedup vs baseline: 2.4941x; 1.1034x over previous
#include <cuda_runtime.h>
#include <cuda_fp16.h>
#include <cstdint>

#define BATCH 4
#define SEQ 2048
#define DIM 1024
#define HEADS 16
#define DHEAD 64
#define INNER 1024
#define TOKENS (BATCH * SEQ)
#define ATT_SCALE 0.125f

// ---------------------------------------------------------------------------
// Scratch (allocation-free device globals) — all single fp16.
// ---------------------------------------------------------------------------
__device__ __half g_xw[TOKENS * DIM];
__device__ __half g_qw[TOKENS * INNER];
__device__ __half g_kw[TOKENS * INNER];
__device__ __half g_vw[TOKENS * INNER];
__device__ __half g_ow[TOKENS * INNER];
// fused QKV weight, transposed: rows 0-1023 = Wq^T, 1024-3071 = Wkv^T
__device__ __half g_wt[3 * INNER * DIM];
__device__ __half g_wot[DIM * INNER];

// ---------------------------------------------------------------------------
// Helpers (base-target PTX only: ldmatrix / mma.sync / cp.async)
// ---------------------------------------------------------------------------
__device__ __forceinline__ uint32_t smem_u32(const void* p) {
    uint32_t a;
    asm("{ .reg .u64 t; cvta.to.shared.u64 t, %1; cvt.u32.u64 %0, t; }"
        : "=r"(a) : "l"(p));
    return a;
}

__device__ __forceinline__ void ldm_x4(uint32_t* r, uint32_t addr) {
    asm volatile("ldmatrix.sync.aligned.m8n8.x4.shared.b16 {%0,%1,%2,%3}, [%4];"
                 : "=r"(r[0]), "=r"(r[1]), "=r"(r[2]), "=r"(r[3]) : "r"(addr));
}

__device__ __forceinline__ void ldm_x4_t(uint32_t* r, uint32_t addr) {
    asm volatile("ldmatrix.sync.aligned.m8n8.x4.trans.shared.b16 {%0,%1,%2,%3}, [%4];"
                 : "=r"(r[0]), "=r"(r[1]), "=r"(r[2]), "=r"(r[3]) : "r"(addr));
}

// fp16 inputs, fp32 accumulate
__device__ __forceinline__ void mma16816(float* c, const uint32_t* a, const uint32_t* b) {
    asm volatile(
        "mma.sync.aligned.m16n8k16.row.col.f32.f16.f16.f32 "
        "{%0,%1,%2,%3}, {%4,%5,%6,%7}, {%8,%9}, {%0,%1,%2,%3};"
        : "+f"(c[0]), "+f"(c[1]), "+f"(c[2]), "+f"(c[3])
        : "r"(a[0]), "r"(a[1]), "r"(a[2]), "r"(a[3]), "r"(b[0]), "r"(b[1]));
}

__device__ __forceinline__ void cp_async16(uint32_t saddr, const void* gaddr) {
    asm volatile("cp.async.cg.shared.global [%0], [%1], 16;"
                 :: "r"(saddr), "l"(gaddr) : "memory");
}
__device__ __forceinline__ void cp_commit() {
    asm volatile("cp.async.commit_group;" ::: "memory");
}
template <int N>
__device__ __forceinline__ void cp_wait() {
    asm volatile("cp.async.wait_group %0;" :: "n"(N) : "memory");
}

__device__ __forceinline__ uint32_t pack_h2(float x, float y) {
    __half2 H(__float2half_rn(x), __float2half_rn(y));
    return *(uint32_t*)&H;
}

// 128B-row swizzle (flash tiles): 8 x 16B chunks per row, chunk ^= row (mod 8)
#define FSWZ(row, chunk) (((row) << 7) + ((((chunk) ^ (row)) & 7) << 4))
// 64B-row swizzle (gemm tiles): 4 x 16B chunks per row, chunk ^= (row>>1)&3
#define HSWZ(row, chunk) (((row) << 6) + (((chunk) ^ (((row) >> 1) & 3)) << 4))

// ---------------------------------------------------------------------------
// Prep: cast x to fp16
// ---------------------------------------------------------------------------
__global__ void cast_x_kernel(const float* __restrict__ in,
                              __half* __restrict__ o) {
    int i = (blockIdx.x * blockDim.x + threadIdx.x) * 4;
    float4 v = *(const float4*)(in + i);
    *(uint32_t*)(o + i)     = pack_h2(v.x, v.y);
    *(uint32_t*)(o + i + 2) = pack_h2(v.z, v.w);
}

// ---------------------------------------------------------------------------
// Prep: transpose W[K,N] -> WT[N,K], single fp16
// ---------------------------------------------------------------------------
__global__ void transpose_h_kernel(const float* __restrict__ W,
                                   __half* __restrict__ WT,
                                   int K, int N) {
    __shared__ float t[32][33];
    int k0 = blockIdx.x * 32, n0 = blockIdx.y * 32;
    int x = threadIdx.x, y = threadIdx.y;
#pragma unroll
    for (int j = 0; j < 32; j += 8)
        t[y + j][x] = W[(size_t)(k0 + y + j) * N + n0 + x];
    __syncthreads();
#pragma unroll
    for (int j = 0; j < 32; j += 8)
        WT[(size_t)(n0 + y + j) * K + k0 + x] = __float2half_rn(t[x][y + j]);
}

// ---------------------------------------------------------------------------
// HMMA fp16 GEMM:  C[M,N] = A[M,K] @ BT[N,K]^T  (fp32 accumulate)
// CTA tile 128x128, 512 threads, 16 warps = 4(M) x 4(N), warp tile 32x32.
// k-block 32, 4-stage cp.async ring (64 KB). One sync per k-block.
// Output: fp32 Cf (+bias) if non-null; else QKV epilogue by 1024-col segment:
//   seg0 -> q fp16 scaled by ATT_SCALE; seg1 -> k fp16; seg2 -> v fp16.
// ---------------------------------------------------------------------------
#define HT_TK 32
#define HT_TILE 8192                     // [128 rows][32 fp16] = 8 KB
#define HT_STAGE (2 * HT_TILE)           // A + B = 16 KB
#define HT_NSTG 4
#define HT_SMEM (HT_NSTG * HT_STAGE)     // 64 KB

__global__ __launch_bounds__(512)
void gemm_tc(const __half* __restrict__ Aw,
             const __half* __restrict__ Bw,
             float* __restrict__ Cf, const float* __restrict__ bias,
             __half* __restrict__ Sq, __half* __restrict__ Sk,
             __half* __restrict__ Sv,
             int N, int K)
{
    extern __shared__ char smem[];
    const uint32_t sb = smem_u32(smem);
    const int tid = threadIdx.x;
    const int wid = tid >> 5;
    const int lane = tid & 31;
    const int m0 = blockIdx.y * 128;
    const int n0 = blockIdx.x * 128;
    const int nkb = K / HT_TK;

    const int wm = (wid & 3) * 32;
    const int wn = (wid >> 2) * 32;

    const int lrow = tid >> 2;
    const int lch  = tid & 3;
    const uint32_t lsw = HSWZ(lrow, lch);

    auto load_stage = [&](int st, int kb) {
        const uint32_t stg = sb + st * HT_STAGE;
        const size_t kc = (size_t)kb * HT_TK + lch * 8;
        cp_async16(stg + lsw,           Aw + (size_t)(m0 + lrow) * K + kc);
        cp_async16(stg + HT_TILE + lsw, Bw + (size_t)(n0 + lrow) * K + kc);
    };

    float acc[2][4][4];
#pragma unroll
    for (int i = 0; i < 2; i++)
#pragma unroll
        for (int j = 0; j < 4; j++)
#pragma unroll
            for (int e = 0; e < 4; e++) acc[i][j][e] = 0.f;

    const int a_row = lane & 15;
    const int a_chk = lane >> 4;
    const int b_row = (lane & 7) + ((lane >> 4) << 3);
    const int b_chk = (lane >> 3) & 1;

    load_stage(0, 0); cp_commit();
    load_stage(1, 1); cp_commit();
    load_stage(2, 2); cp_commit();

    for (int kb = 0; kb < nkb; kb++) {
        if (kb < nkb - 2)       cp_wait<2>();
        else if (kb == nkb - 2) cp_wait<1>();
        else                    cp_wait<0>();
        __syncthreads();

        if (kb + 3 < nkb) {
            load_stage((kb + 3) & (HT_NSTG - 1), kb + 3);
            cp_commit();
        }

        const uint32_t stg = sb + (kb & (HT_NSTG - 1)) * HT_STAGE;
        const uint32_t sAw = stg;
        const uint32_t sBw = stg + HT_TILE;

#pragma unroll
        for (int kk = 0; kk < 2; kk++) {
            uint32_t aw[2][4], bw[2][4];
#pragma unroll
            for (int mt = 0; mt < 2; mt++) {
                int r = wm + mt * 16 + a_row;
                int c = kk * 2 + a_chk;
                ldm_x4(aw[mt], sAw + HSWZ(r, c));
            }
#pragma unroll
            for (int ng = 0; ng < 2; ng++) {
                int r = wn + ng * 16 + b_row;
                int c = kk * 2 + b_chk;
                ldm_x4(bw[ng], sBw + HSWZ(r, c));
            }
#pragma unroll
            for (int mt = 0; mt < 2; mt++)
#pragma unroll
                for (int nt = 0; nt < 4; nt++)
                    mma16816(acc[mt][nt], aw[mt], &bw[nt >> 1][(nt & 1) * 2]);
        }
        __syncthreads();
    }

    const int erow = lane >> 2;
    const int ecol = (lane & 3) * 2;

    if (Cf) {
        // fp32 output with bias
#pragma unroll
        for (int mt = 0; mt < 2; mt++) {
#pragma unroll
            for (int nt = 0; nt < 4; nt++) {
                int gcol = n0 + wn + nt * 8 + ecol;
                float b0 = 0.f, b1 = 0.f;
                if (bias) { b0 = bias[gcol]; b1 = bias[gcol + 1]; }
                int r0 = m0 + wm + mt * 16 + erow;
                float2 v0 = make_float2(acc[mt][nt][0] + b0, acc[mt][nt][1] + b1);
                float2 v1 = make_float2(acc[mt][nt][2] + b0, acc[mt][nt][3] + b1);
                *(float2*)(Cf + (size_t)r0 * N + gcol)       = v0;
                *(float2*)(Cf + (size_t)(r0 + 8) * N + gcol) = v1;
            }
        }
    } else {
        const int seg = n0 >> 10;      // 0:q  1:k  2:v
        const int c0 = n0 & 1023;
        const float sc = (seg == 0) ? ATT_SCALE : 1.0f;
        __half* D = (seg == 0) ? Sq : (seg == 1) ? Sk : Sv;
#pragma unroll
        for (int mt = 0; mt < 2; mt++) {
#pragma unroll
            for (int nt = 0; nt < 4; nt++) {
                int r0 = m0 + wm + mt * 16 + erow;
                int lcol = c0 + wn + nt * 8 + ecol;
                *(uint32_t*)(D + (size_t)r0 * 1024 + lcol) =
                    pack_h2(acc[mt][nt][0] * sc, acc[mt][nt][1] * sc);
                *(uint32_t*)(D + (size_t)(r0 + 8) * 1024 + lcol) =
                    pack_h2(acc[mt][nt][2] * sc, acc[mt][nt][3] * sc);
            }
        }
    }
}

// ---------------------------------------------------------------------------
// Flash attention on mma.sync, single fp16 Q/K/V/P (fp32 accumulate).
// CTA = 128 q rows x one (b,h). 8 warps, 16 rows each. K-chunks of 64,
// 3-stage cp.async KV ring. smem = 16 + 48 = 64 KB -> 2 CTAs/SM.
// ---------------------------------------------------------------------------
#define FA_BQ 128
#define FA_BK 64
#define FA_NC (SEQ / FA_BK)
#define FA_KVST 16384
#define FA_SMEM (16384 + 3 * FA_KVST)

__global__ __launch_bounds__(256, 2)
void flash_tc(const __half* __restrict__ Qw,
              const __half* __restrict__ Kw, const __half* __restrict__ Vw,
              __half* __restrict__ Ow)
{
    extern __shared__ char smem[];
    const uint32_t sb = smem_u32(smem);
    const int tid = threadIdx.x;
    const int wid = tid >> 5;
    const int lane = tid & 31;
    const int qt = blockIdx.x;
    const int b  = blockIdx.y >> 4;
    const int h  = blockIdx.y & 15;

    const size_t base_q  = (size_t)(b * SEQ + qt * FA_BQ) * INNER + h * DHEAD;
    const size_t base_kv = (size_t)b * SEQ * INNER + h * DHEAD;

    // ---- Q load (16 KB) ----
    {
        int row = tid >> 3, chunk = tid & 7;
#pragma unroll
        for (int p = 0; p < 4; p++) {
            int r = row + p * 32;
            cp_async16(sb + FSWZ(r, chunk), Qw + base_q + (size_t)r * INNER + chunk * 8);
        }
    }
    auto load_kv = [&](int st, int kc) {
        const uint32_t stg = sb + 16384 + st * FA_KVST;
        int row = tid >> 3, chunk = tid & 7;
        size_t gk = base_kv + (size_t)(kc * FA_BK) * INNER + chunk * 8;
#pragma unroll
        for (int p = 0; p < 2; p++) {
            int r = row + p * 32;
            size_t go = gk + (size_t)r * INNER;
            cp_async16(stg +        FSWZ(r, chunk), Kw + go);
            cp_async16(stg + 8192 + FSWZ(r, chunk), Vw + go);
        }
    };
    load_kv(0, 0); cp_commit();
    load_kv(1, 1); cp_commit();

    uint32_t qf[4][4];
    float oacc[8][4];
#pragma unroll
    for (int j = 0; j < 8; j++)
#pragma unroll
        for (int e = 0; e < 4; e++) oacc[j][e] = 0.f;
    float m0 = -1e30f, m1 = -1e30f, l0 = 0.f, l1 = 0.f;

    for (int kc = 0; kc < FA_NC; kc++) {
        if (kc + 1 < FA_NC) cp_wait<1>(); else cp_wait<0>();
        __syncthreads();

        if (kc == 0) {
#pragma unroll
            for (int kk = 0; kk < 4; kk++) {
                int r = wid * 16 + (lane & 15);
                int c = 2 * kk + (lane >> 4);
                ldm_x4(qf[kk], sb + FSWZ(r, c));
            }
        }
        const uint32_t stg = sb + 16384 + (kc % 3) * FA_KVST;

        // ---- S = Q @ K^T ----
        float sacc[8][4];
#pragma unroll
        for (int t = 0; t < 8; t++)
#pragma unroll
            for (int e = 0; e < 4; e++) sacc[t][e] = 0.f;
#pragma unroll
        for (int kk = 0; kk < 4; kk++) {
            uint32_t kb[4][4];
#pragma unroll
            for (int G = 0; G < 4; G++) {
                int r = 16 * G + ((lane >> 4) << 3) + (lane & 7);
                int c = 2 * kk + ((lane >> 3) & 1);
                ldm_x4(kb[G], stg + FSWZ(r, c));
            }
#pragma unroll
            for (int t = 0; t < 8; t++)
                mma16816(sacc[t], qf[kk], &kb[t >> 1][(t & 1) * 2]);
        }

        // ---- online softmax ----
        float mx0 = -1e30f, mx1 = -1e30f;
#pragma unroll
        for (int t = 0; t < 8; t++) {
            mx0 = fmaxf(mx0, fmaxf(sacc[t][0], sacc[t][1]));
            mx1 = fmaxf(mx1, fmaxf(sacc[t][2], sacc[t][3]));
        }
        mx0 = fmaxf(mx0, __shfl_xor_sync(0xffffffffu, mx0, 1));
        mx0 = fmaxf(mx0, __shfl_xor_sync(0xffffffffu, mx0, 2));
        mx1 = fmaxf(mx1, __shfl_xor_sync(0xffffffffu, mx1, 1));
        mx1 = fmaxf(mx1, __shfl_xor_sync(0xffffffffu, mx1, 2));
        float mn0 = fmaxf(m0, mx0), mn1 = fmaxf(m1, mx1);
        float a0 = __expf(m0 - mn0), a1 = __expf(m1 - mn1);
        m0 = mn0; m1 = mn1;
        float s0 = 0.f, s1 = 0.f;
#pragma unroll
        for (int t = 0; t < 8; t++) {
            sacc[t][0] = __expf(sacc[t][0] - mn0); s0 += sacc[t][0];
            sacc[t][1] = __expf(sacc[t][1] - mn0); s0 += sacc[t][1];
            sacc[t][2] = __expf(sacc[t][2] - mn1); s1 += sacc[t][2];
            sacc[t][3] = __expf(sacc[t][3] - mn1); s1 += sacc[t][3];
        }
        s0 += __shfl_xor_sync(0xffffffffu, s0, 1);
        s0 += __shfl_xor_sync(0xffffffffu, s0, 2);
        s1 += __shfl_xor_sync(0xffffffffu, s1, 1);
        s1 += __shfl_xor_sync(0xffffffffu, s1, 2);
        l0 = l0 * a0 + s0;
        l1 = l1 * a1 + s1;
#pragma unroll
        for (int j = 0; j < 8; j++) {
            oacc[j][0] *= a0; oacc[j][1] *= a0;
            oacc[j][2] *= a1; oacc[j][3] *= a1;
        }

        // ---- O += P @ V (P single fp16) ----
#pragma unroll
        for (int s = 0; s < 4; s++) {
            uint32_t ph[4];
            ph[0] = pack_h2(sacc[2 * s][0],     sacc[2 * s][1]);
            ph[1] = pack_h2(sacc[2 * s][2],     sacc[2 * s][3]);
            ph[2] = pack_h2(sacc[2 * s + 1][0], sacc[2 * s + 1][1]);
            ph[3] = pack_h2(sacc[2 * s + 1][2], sacc[2 * s + 1][3]);
            uint32_t vb[4][4];
#pragma unroll
            for (int J = 0; J < 4; J++) {
                int r = 16 * s + (lane & 7) + ((lane >> 3) & 1) * 8;
                int c = 2 * J + (lane >> 4);
                ldm_x4_t(vb[J], stg + 8192 + FSWZ(r, c));
            }
#pragma unroll
            for (int j = 0; j < 8; j++)
                mma16816(oacc[j], ph, &vb[j >> 1][(j & 1) * 2]);
        }

        if (kc + 2 < FA_NC) {
            load_kv((kc + 2) % 3, kc + 2);
            cp_commit();
        }
    }

    // ---- normalize + write O (single fp16) ----
    float inv0 = 1.f / l0, inv1 = 1.f / l1;
    int r = lane >> 2;
    size_t row0 = (size_t)(b * SEQ + qt * FA_BQ + wid * 16 + r);
    size_t row1 = row0 + 8;
    int colb = h * DHEAD + (lane & 3) * 2;
#pragma unroll
    for (int j = 0; j < 8; j++) {
        *(uint32_t*)(Ow + row0 * INNER + colb + j * 8) =
            pack_h2(oacc[j][0] * inv0, oacc[j][1] * inv0);
        *(uint32_t*)(Ow + row1 * INNER + colb + j * 8) =
            pack_h2(oacc[j][2] * inv1, oacc[j][3] * inv1);
    }
}

// ---------------------------------------------------------------------------
extern "C" void kernel_launch(void* const* d_in, const int* in_sizes, int n_in,
                              void* d_out, int out_size)
{
    const float* x   = (const float*)d_in[0];
    const float* Wq  = (const float*)d_in[1];
    const float* Wkv = (const float*)d_in[2];
    const float* Wo  = (const float*)d_in[3];
    const float* bo  = (const float*)d_in[4];
    float* out = (float*)d_out;

    __half *xw, *qw, *kw, *vw, *ow, *wt, *wot;
    cudaGetSymbolAddress((void**)&xw, g_xw);
    cudaGetSymbolAddress((void**)&qw, g_qw);
    cudaGetSymbolAddress((void**)&kw, g_kw);
    cudaGetSymbolAddress((void**)&vw, g_vw);
    cudaGetSymbolAddress((void**)&ow, g_ow);
    cudaGetSymbolAddress((void**)&wt, g_wt);
    cudaGetSymbolAddress((void**)&wot, g_wot);

    cudaFuncSetAttribute(gemm_tc, cudaFuncAttributeMaxDynamicSharedMemorySize, HT_SMEM);
    cudaFuncSetAttribute(flash_tc, cudaFuncAttributeMaxDynamicSharedMemorySize, FA_SMEM);

    // prep: cast x; transpose Wq/Wkv into fused [3072,1024] fp16 + Wo^T fp16
    cast_x_kernel<<<TOKENS * DIM / (256 * 4), 256>>>(x, xw);
    transpose_h_kernel<<<dim3(DIM / 32, INNER / 32), dim3(32, 8)>>>(
        Wq, wt, DIM, INNER);
    transpose_h_kernel<<<dim3(DIM / 32, 2 * INNER / 32), dim3(32, 8)>>>(
        Wkv, wt + (size_t)INNER * DIM, DIM, 2 * INNER);
    transpose_h_kernel<<<dim3(INNER / 32, DIM / 32), dim3(32, 8)>>>(
        Wo, wot, INNER, DIM);

    // fused [q|k|v] = x @ [Wq|Wkv]  (q scaled; fp16 out)
    gemm_tc<<<dim3(3 * INNER / 128, TOKENS / 128), 512, HT_SMEM>>>(
        xw, wt, nullptr, nullptr, qw, kw, vw, 3 * INNER, DIM);

    // attention on tensor cores
    flash_tc<<<dim3(SEQ / FA_BQ, BATCH * HEADS), 256, FA_SMEM>>>(qw, kw, vw, ow);

    // out = O @ Wo + bo  -> fp32
    gemm_tc<<<dim3(DIM / 128, TOKENS / 128), 512, HT_SMEM>>>(
        ow, wot, out, bo, nullptr, nullptr, nullptr, DIM, INNER);
}